// round 14
// baseline (speedup 1.0000x reference)
#include <cuda_runtime.h>
#include <math.h>

#define SEQ  1024
#define NF   256
#define H    1024
#define G4   4096
#define OUTN 1024
#define NB   128   // persistent CTAs (1/SM; all co-resident)
#define JPB  8     // h indices per CTA
#define NLINES 8   // arrival counter lines per step
#define PERLINE (NB / NLINES)   // 16 CTAs arrive per line

typedef unsigned long long u64;

// ---------------- device scratch ----------------
__device__ float    g_gx[(size_t)SEQ * G4];        // x@W_ih^T + b_ih + b_hh (16 MB)
__device__ float    g_h[(size_t)(SEQ + 1) * H];    // row0 = BSS zeros (never written)
__device__ float    g_logits[(size_t)SEQ * OUTN];
__device__ float    g_lse[SEQ];
__device__ u64      g_sorted[(size_t)SEQ * OUTN];  // per-row descending (key<<32 | 1023-idx)
__device__ unsigned g_done[(size_t)(SEQ + 1) * NLINES * 32]; // 8 padded lines/step (memset/launch)

__device__ __forceinline__ float sigm(float x) { return 1.0f / (1.0f + __expf(-x)); }

__device__ __forceinline__ unsigned ld_acq(const unsigned* p) {
    unsigned v;
    asm volatile("ld.acquire.gpu.global.u32 %0, [%1];" : "=r"(v) : "l"(p) : "memory");
    return v;
}
__device__ __forceinline__ void red_rel(unsigned* p) {
    asm volatile("red.release.gpu.global.add.u32 [%0], 1;" :: "l"(p) : "memory");
}
__device__ __forceinline__ unsigned* done_ctr(int step, int line) {
    return &g_done[((size_t)step * NLINES + line) * 32];
}

// ---------------- Kernel A: gx[t][r] = b_ih[r]+b_hh[r] + X[t]·W_ih[r] ----------------
__global__ void precompute_gx(const float* __restrict__ X,
                              const float* __restrict__ Wih,
                              const float* __restrict__ bih,
                              const float* __restrict__ bhh) {
    __shared__ float Xs[32 * NF];
    const int r  = blockIdx.x * 256 + threadIdx.x;
    const int t0 = blockIdx.y * 32;

    for (int i = threadIdx.x; i < 32 * NF; i += 256)
        Xs[i] = X[(size_t)t0 * NF + i];
    __syncthreads();

    const float bias = bih[r] + bhh[r];
    float acc[32];
#pragma unroll
    for (int tt = 0; tt < 32; tt++) acc[tt] = bias;

    const float4* Wr = (const float4*)(Wih + (size_t)r * NF);
    for (int k4 = 0; k4 < NF / 4; k4++) {
        float4 wv = Wr[k4];
#pragma unroll
        for (int tt = 0; tt < 32; tt++) {
            float4 xv = *(const float4*)&Xs[tt * NF + k4 * 4];
            acc[tt] += wv.x * xv.x + wv.y * xv.y + wv.z * xv.z + wv.w * xv.w;
        }
    }
#pragma unroll
    for (int tt = 0; tt < 32; tt++)
        g_gx[(size_t)(t0 + tt) * G4 + r] = acc[tt];
}

// ---------------- Kernel B: persistent LSTM (proven R5/R9 + 8-line arrival split) ----
__global__ void __launch_bounds__(256, 1)
lstm_recurrence(const float* __restrict__ enc,
                const float* __restrict__ Whh,
                const float* __restrict__ Wout,
                const float* __restrict__ bout) {
    extern __shared__ float smem[];
    float* Whh_s  = smem;               // [32 rows][1024]
    float* Wout_s = smem + 8 * 4 * H;   // [8][1024]
    float* hs     = Wout_s + 8 * H;     // [1024]

    const int b = blockIdx.x, tid = threadIdx.x;
    const int w = tid >> 5, l = tid & 31;
    const int j = b * JPB + w;
    const int myline = b & (NLINES - 1);

    // ---- stage weights ----
    for (int rg = 0; rg < 32; rg++) {
        int ww = rg >> 2, g = rg & 3;
        int grow = g * H + b * JPB + ww;
        ((float4*)&Whh_s[(size_t)rg * H])[tid] = ((const float4*)&Whh[(size_t)grow * H])[tid];
    }
    for (int ww = 0; ww < 8; ww++)
        ((float4*)&Wout_s[ww * H])[tid] = ((const float4*)&Wout[(size_t)(b * JPB + ww) * H])[tid];

    const float c0j   = enc[(size_t)(SEQ - 1) * H + j];
    const float boutj = bout[j];

    float gxv_next = (l < 4) ? g_gx[(size_t)0 * G4 + l * H + j] : 0.0f;  // prefetch t=0
    __syncthreads();

    float hreg[32];

    for (int t = 0; t < SEQ; t++) {
        // ---- wait for h_t: 8 threads each acquire-poll one padded counter line ----
        if (t > 0) {
            if (tid < NLINES) { while (ld_acq(done_ctr(t, tid)) < PERLINE) {} }
            __syncthreads();
        }

        // ---- stage h_t, rotate prefetched gx ----
        ((float4*)hs)[tid] = ((const float4*)&g_h[(size_t)t * H])[tid];
        float gxv = gxv_next;
        __syncthreads();

        // prefetch gx[t+1] (off critical path)
        if (t + 1 < SEQ && l < 4) gxv_next = g_gx[(size_t)(t + 1) * G4 + l * H + j];

        // ---- 4 gate dot-products for this warp's j ----
        float a0 = 0.f, a1 = 0.f, a2 = 0.f, a3 = 0.f;
#pragma unroll
        for (int cc = 0; cc < 8; cc++) {
            int c = (cc * 32 + l) * 4;
            float4 hv = *(float4*)&hs[c];
            hreg[cc * 4 + 0] = hv.x; hreg[cc * 4 + 1] = hv.y;
            hreg[cc * 4 + 2] = hv.z; hreg[cc * 4 + 3] = hv.w;
            float4 w0 = *(float4*)&Whh_s[(w * 4 + 0) * H + c];
            float4 w1 = *(float4*)&Whh_s[(w * 4 + 1) * H + c];
            float4 w2 = *(float4*)&Whh_s[(w * 4 + 2) * H + c];
            float4 w3 = *(float4*)&Whh_s[(w * 4 + 3) * H + c];
            a0 += w0.x * hv.x + w0.y * hv.y + w0.z * hv.z + w0.w * hv.w;
            a1 += w1.x * hv.x + w1.y * hv.y + w1.z * hv.z + w1.w * hv.w;
            a2 += w2.x * hv.x + w2.y * hv.y + w2.z * hv.z + w2.w * hv.w;
            a3 += w3.x * hv.x + w3.y * hv.y + w3.z * hv.z + w3.w * hv.w;
        }
#pragma unroll
        for (int off = 16; off; off >>= 1) {
            a0 += __shfl_down_sync(0xffffffffu, a0, off);
            a1 += __shfl_down_sync(0xffffffffu, a1, off);
            a2 += __shfl_down_sync(0xffffffffu, a2, off);
            a3 += __shfl_down_sync(0xffffffffu, a3, off);
        }
        float gx0 = __shfl_sync(0xffffffffu, gxv, 0);
        float gx1 = __shfl_sync(0xffffffffu, gxv, 1);
        float gx2 = __shfl_sync(0xffffffffu, gxv, 2);
        float gx3 = __shfl_sync(0xffffffffu, gxv, 3);
        if (l == 0) {
            float ig = sigm(a0 + gx0);
            float fg = sigm(a1 + gx1);
            float gg = tanhf(a2 + gx2);
            float og = sigm(a3 + gx3);
            float c  = fg * c0j + ig * gg;
            g_h[(size_t)(t + 1) * H + j] = og * tanhf(c);
        }
        __syncthreads();

        // ---- arrive: one release-red per CTA on its line (16 CTAs/line, 8 lines) ----
        if (tid == 0) red_rel(done_ctr(t + 1, myline));

        // ---- hidden in barrier slack: logits[t-1] = h_t · Wout_j ----
        if (t > 0) {
            float s = 0.f;
#pragma unroll
            for (int cc = 0; cc < 8; cc++) {
                int c = (cc * 32 + l) * 4;
                float4 wv = *(float4*)&Wout_s[w * H + c];
                s += wv.x * hreg[cc * 4 + 0] + wv.y * hreg[cc * 4 + 1]
                   + wv.z * hreg[cc * 4 + 2] + wv.w * hreg[cc * 4 + 3];
            }
#pragma unroll
            for (int off = 16; off; off >>= 1) s += __shfl_down_sync(0xffffffffu, s, off);
            if (l == 0) g_logits[(size_t)(t - 1) * OUTN + j] = s + boutj;
        }
    }

    // ---- epilogue: logits[SEQ-1] from h_SEQ ----
    if (tid < NLINES) { while (ld_acq(done_ctr(SEQ, tid)) < PERLINE) {} }
    __syncthreads();
    ((float4*)hs)[tid] = ((const float4*)&g_h[(size_t)SEQ * H])[tid];
    __syncthreads();
    {
        float s = 0.f;
#pragma unroll
        for (int cc = 0; cc < 8; cc++) {
            int c = (cc * 32 + l) * 4;
            float4 hv = *(float4*)&hs[c];
            float4 wv = *(float4*)&Wout_s[w * H + c];
            s += wv.x * hv.x + wv.y * hv.y + wv.z * hv.z + wv.w * hv.w;
        }
#pragma unroll
        for (int off = 16; off; off >>= 1) s += __shfl_down_sync(0xffffffffu, s, off);
        if (l == 0) g_logits[(size_t)(SEQ - 1) * OUTN + j] = s + boutj;
    }
}

// ---------------- Kernel C: per-row logsumexp ----------------
__global__ void row_lse() {
    const int t = blockIdx.x, tid = threadIdx.x, w = tid >> 5, l = tid & 31;
    __shared__ float red[8];
    float v[4];
#pragma unroll
    for (int k = 0; k < 4; k++) v[k] = g_logits[(size_t)t * OUTN + tid + k * 256];
    float m = fmaxf(fmaxf(v[0], v[1]), fmaxf(v[2], v[3]));
#pragma unroll
    for (int off = 16; off; off >>= 1) m = fmaxf(m, __shfl_xor_sync(0xffffffffu, m, off));
    if (l == 0) red[w] = m;
    __syncthreads();
    float M = red[0];
#pragma unroll
    for (int i = 1; i < 8; i++) M = fmaxf(M, red[i]);
    float s = 0.f;
#pragma unroll
    for (int k = 0; k < 4; k++) s += expf(v[k] - M);
#pragma unroll
    for (int off = 16; off; off >>= 1) s += __shfl_xor_sync(0xffffffffu, s, off);
    __syncthreads();
    if (l == 0) red[w] = s;
    __syncthreads();
    if (tid == 0) {
        float S = 0.f;
#pragma unroll
        for (int i = 0; i < 8; i++) S += red[i];
        g_lse[t] = M + logf(S);
    }
}

// ---------------- Kernel S: bitonic sort each logits row (descending u64 keys) ----------------
// key = (monotone(float) << 32) | (1023 - idx)  -> max key = (max value, min index)
__global__ void sort_rows() {
    __shared__ u64 key[OUTN];
    const int t = blockIdx.x, tid = threadIdx.x;

    for (int i = tid; i < OUTN; i += 256) {
        unsigned u = __float_as_uint(g_logits[(size_t)t * OUTN + i]);
        unsigned m = (u & 0x80000000u) ? ~u : (u | 0x80000000u);
        key[i] = ((u64)m << 32) | (u64)(OUTN - 1 - i);
    }
    __syncthreads();

    for (int k = 2; k <= OUTN; k <<= 1) {
        for (int jj = k >> 1; jj > 0; jj >>= 1) {
            for (int i = tid; i < OUTN; i += 256) {
                int ix = i ^ jj;
                if (ix > i) {
                    bool descend = (i & k) == 0;
                    u64 a = key[i], c = key[ix];
                    bool sw = descend ? (a < c) : (a > c);
                    if (sw) { key[i] = c; key[ix] = a; }
                }
            }
            __syncthreads();
        }
    }

    for (int i = tid; i < OUTN; i += 256)
        g_sorted[(size_t)t * OUTN + i] = key[i];
}

// ---------------- Kernel D: ballot-based tour selection over sorted candidates ----------------
__global__ void tour_select(float* __restrict__ out, int out_size) {
    __shared__ unsigned vis[32];
    const int l = threadIdx.x;
    vis[l] = 0;
    __syncwarp();

    u64 cur = g_sorted[l];       // rank-l candidate of row 0
    float lse_c = g_lse[0];

    for (int t = 0; t < SEQ; t++) {
        u64 nxt = 0; float lse_n = 0.f;
        if (t + 1 < SEQ) {
            nxt   = g_sorted[(size_t)(t + 1) * OUTN + l];
            lse_n = g_lse[t + 1];
        }

        u64 key = cur;
        int batch = 0;
        unsigned ballot;
        for (;;) {
            unsigned idx  = OUTN - 1 - (unsigned)(key & 0xFFFFFFFFu);
            bool unvis = ((vis[idx >> 5] >> (idx & 31)) & 1u) == 0u;
            ballot = __ballot_sync(0xffffffffu, unvis);
            if (ballot) break;
            batch++;                               // rare: top-32*batch all visited
            key = g_sorted[(size_t)t * OUTN + batch * 32 + l];
        }
        int wl = __ffs(ballot) - 1;                // lowest lane = best rank
        u64 wkey = __shfl_sync(0xffffffffu, key, wl);
        unsigned widx = OUTN - 1 - (unsigned)(wkey & 0xFFFFFFFFu);
        if (l == 0) {
            unsigned m = (unsigned)(wkey >> 32);
            unsigned u = (m & 0x80000000u) ? (m ^ 0x80000000u) : ~m;
            float val = __uint_as_float(u);
            if (t < out_size)       out[t] = (float)widx;
            if (SEQ + t < out_size) out[SEQ + t] = val - lse_c;
            vis[widx >> 5] |= 1u << (widx & 31);
        }
        __syncwarp();

        cur = nxt; lse_c = lse_n;
    }
}

// ---------------- launch ----------------
extern "C" void kernel_launch(void* const* d_in, const int* in_sizes, int n_in,
                              void* d_out, int out_size) {
    const float* X    = (const float*)d_in[0];
    const float* enc  = (const float*)d_in[1];
    const float* Wih  = (const float*)d_in[2];
    const float* Whh  = (const float*)d_in[3];
    const float* bih  = (const float*)d_in[4];
    const float* bhh  = (const float*)d_in[5];
    const float* Wout = (const float*)d_in[6];
    const float* bout = (const float*)d_in[7];
    float* out = (float*)d_out;

    // per-launch resets (graph-capturable async memsets, same pattern as passing R5/R9)
    void* doneAddr = nullptr; cudaGetSymbolAddress(&doneAddr, g_done);
    cudaMemsetAsync(doneAddr, 0, (size_t)(SEQ + 1) * NLINES * 32 * sizeof(unsigned));
    void* hAddr = nullptr; cudaGetSymbolAddress(&hAddr, g_h);
    cudaMemsetAsync(hAddr, 0, H * sizeof(float));   // h_0 = 0

    size_t smemB = (size_t)(8 * 4 * H + 8 * H + H) * sizeof(float);  // 168 KB
    cudaFuncSetAttribute(lstm_recurrence, cudaFuncAttributeMaxDynamicSharedMemorySize, (int)smemB);

    precompute_gx<<<dim3(16, 32), 256>>>(X, Wih, bih, bhh);
    lstm_recurrence<<<NB, 256, smemB>>>(enc, Whh, Wout, bout);
    row_lse<<<SEQ, 256>>>();
    sort_rows<<<SEQ, 256>>>();
    tour_select<<<1, 32>>>(out, out_size);
}

// round 15
// speedup vs baseline: 1.0219x; 1.0219x over previous
#include <cuda_runtime.h>
#include <math.h>

#define SEQ  1024
#define NF   256
#define H    1024
#define G4   4096
#define OUTN 1024
#define NB   128   // persistent CTAs (1/SM; all co-resident)
#define JPB  8     // h indices per CTA
#define NLINES 8
#define PERLINE (NB / NLINES)

typedef unsigned long long u64;

// ---------------- device scratch ----------------
__device__ float    g_gx[(size_t)SEQ * G4];
__device__ float    g_h[(size_t)(SEQ + 1) * H];
__device__ float    g_logits[(size_t)SEQ * OUTN];
__device__ float    g_lse[SEQ];
__device__ u64      g_sorted[(size_t)SEQ * OUTN];
__device__ unsigned g_done[(size_t)(SEQ + 1) * NLINES * 32];  // padded lines (memset/launch)

__device__ __forceinline__ float sigm(float x) { return 1.0f / (1.0f + __expf(-x)); }

__device__ __forceinline__ unsigned ld_acq(const unsigned* p) {
    unsigned v;
    asm volatile("ld.acquire.gpu.global.u32 %0, [%1];" : "=r"(v) : "l"(p) : "memory");
    return v;
}
__device__ __forceinline__ void red_rel(unsigned* p) {
    asm volatile("red.release.gpu.global.add.u32 [%0], 1;" :: "l"(p) : "memory");
}
__device__ __forceinline__ unsigned* done_ctr(int step, int line) {
    return &g_done[((size_t)step * NLINES + line) * 32];
}
__device__ __forceinline__ float dot4(float4 a, float4 b) {
    return a.x * b.x + a.y * b.y + a.z * b.z + a.w * b.w;
}

// ---------------- Kernel A: gx[t][r] = b_ih[r]+b_hh[r] + X[t]·W_ih[r] ----------------
__global__ void precompute_gx(const float* __restrict__ X,
                              const float* __restrict__ Wih,
                              const float* __restrict__ bih,
                              const float* __restrict__ bhh) {
    __shared__ float Xs[32 * NF];
    const int r  = blockIdx.x * 256 + threadIdx.x;
    const int t0 = blockIdx.y * 32;

    for (int i = threadIdx.x; i < 32 * NF; i += 256)
        Xs[i] = X[(size_t)t0 * NF + i];
    __syncthreads();

    const float bias = bih[r] + bhh[r];
    float acc[32];
#pragma unroll
    for (int tt = 0; tt < 32; tt++) acc[tt] = bias;

    const float4* Wr = (const float4*)(Wih + (size_t)r * NF);
    for (int k4 = 0; k4 < NF / 4; k4++) {
        float4 wv = Wr[k4];
#pragma unroll
        for (int tt = 0; tt < 32; tt++)
            acc[tt] += dot4(wv, *(const float4*)&Xs[tt * NF + k4 * 4]);
    }
#pragma unroll
    for (int tt = 0; tt < 32; tt++)
        g_gx[(size_t)(t0 + tt) * G4 + r] = acc[tt];
}

// ---------------- Kernel B: persistent LSTM — Whh in registers, 512 thr, no spill ----
// Warp w: jj = w>>1, half = w&1. Holds all 4 gate rows of j = b*8+jj for its
// 512-column half in 16 float4 registers. Counter barrier = proven R14 scheme.
__global__ void __launch_bounds__(512, 1)
lstm_recurrence(const float* __restrict__ enc,
                const float* __restrict__ Whh,
                const float* __restrict__ Wout,
                const float* __restrict__ bout) {
    __shared__ float4 wout_s[8 * 256];        // 32 KB: Wout rows of this CTA's 8 j
    __shared__ float  hs[H];                  // 4 KB
    __shared__ float  pbuf[8][2][4];          // gate partials [jj][half][gate]
    __shared__ float  pbuf2[16];              // Wout partials [jj*2+half]

    const int b = blockIdx.x, tid = threadIdx.x;
    const int w = tid >> 5, l = tid & 31;
    const int jj = w >> 1, half = w & 1;
    const int j = b * JPB + jj;
    const int myline = b & (NLINES - 1);

    // ---- Whh into registers: wh[g*4+k] = row (g*H+j), cols half*512 + (k*32+l)*4 ----
    float4 wh[16];
    const float4* Whh4 = (const float4*)Whh;
#pragma unroll
    for (int g = 0; g < 4; g++)
#pragma unroll
        for (int k = 0; k < 4; k++)
            wh[g * 4 + k] = Whh4[(size_t)(g * H + j) * 256 + half * 128 + k * 32 + l];

    // ---- Wout rows into smem ----
    const float4* Wout4 = (const float4*)Wout;
    for (int i = tid; i < 8 * 256; i += 512)
        wout_s[i] = Wout4[(size_t)(b * JPB) * 256 + i];

    // tid<8 owns j=b*8+tid for activations/outputs
    float c0j = 0.f, boutj = 0.f, gxr0 = 0.f, gxr1 = 0.f, gxr2 = 0.f, gxr3 = 0.f;
    if (tid < JPB) {
        c0j   = enc[(size_t)(SEQ - 1) * H + b * JPB + tid];
        boutj = bout[b * JPB + tid];
        gxr0 = g_gx[(size_t)0 * G4 + 0 * H + b * JPB + tid];
        gxr1 = g_gx[(size_t)0 * G4 + 1 * H + b * JPB + tid];
        gxr2 = g_gx[(size_t)0 * G4 + 2 * H + b * JPB + tid];
        gxr3 = g_gx[(size_t)0 * G4 + 3 * H + b * JPB + tid];
    }
    __syncthreads();

    const float4* hs4 = (const float4*)hs;

    for (int t = 0; t < SEQ; t++) {
        // A. wait for h_t (t=0: zeros, no wait)
        if (t > 0) {
            if (tid < NLINES) { while (ld_acq(done_ctr(t, tid)) < PERLINE) {} }
        }
        __syncthreads();                              // bar 1

        // B. stage h_t
        if (tid < 256) {
            if (t == 0) ((float4*)hs)[tid] = make_float4(0.f, 0.f, 0.f, 0.f);
            else        ((float4*)hs)[tid] = ((const float4*)(g_h + (size_t)t * H))[tid];
        }
        __syncthreads();                              // bar 2

        // C. gate partials from register weights (this warp's c-half)
        float a0 = 0.f, a1 = 0.f, a2 = 0.f, a3 = 0.f;
#pragma unroll
        for (int k = 0; k < 4; k++) {
            float4 hv = hs4[half * 128 + k * 32 + l];
            a0 += dot4(wh[0 * 4 + k], hv);
            a1 += dot4(wh[1 * 4 + k], hv);
            a2 += dot4(wh[2 * 4 + k], hv);
            a3 += dot4(wh[3 * 4 + k], hv);
        }
#pragma unroll
        for (int off = 16; off; off >>= 1) {
            a0 += __shfl_down_sync(0xffffffffu, a0, off);
            a1 += __shfl_down_sync(0xffffffffu, a1, off);
            a2 += __shfl_down_sync(0xffffffffu, a2, off);
            a3 += __shfl_down_sync(0xffffffffu, a3, off);
        }
        if (l == 0) {
            pbuf[jj][half][0] = a0; pbuf[jj][half][1] = a1;
            pbuf[jj][half][2] = a2; pbuf[jj][half][3] = a3;
        }

        // F. Wout partials for logits[t-1] (reads hs; runs before bar 3, used after)
        float s = 0.f;
#pragma unroll
        for (int k = 0; k < 4; k++) {
            float4 hv = hs4[half * 128 + k * 32 + l];
            s += dot4(wout_s[jj * 256 + half * 128 + k * 32 + l], hv);
        }
#pragma unroll
        for (int off = 16; off; off >>= 1) s += __shfl_down_sync(0xffffffffu, s, off);
        if (l == 0) pbuf2[jj * 2 + half] = s;

        __syncthreads();                              // bar 3

        // E. combine + activations + publish h_{t+1} (threads 0..7)
        if (tid < JPB) {
            float ig = sigm(pbuf[tid][0][0] + pbuf[tid][1][0] + gxr0);
            float fg = sigm(pbuf[tid][0][1] + pbuf[tid][1][1] + gxr1);
            float gg = tanhf(pbuf[tid][0][2] + pbuf[tid][1][2] + gxr2);
            float og = sigm(pbuf[tid][0][3] + pbuf[tid][1][3] + gxr3);
            float c  = fg * c0j + ig * gg;
            g_h[(size_t)(t + 1) * H + b * JPB + tid] = og * tanhf(c);
            // logits[t-1] from Wout partials (h_t)
            if (t > 0)
                g_logits[(size_t)(t - 1) * OUTN + b * JPB + tid] =
                    pbuf2[tid * 2] + pbuf2[tid * 2 + 1] + boutj;
        }
        __syncthreads();                              // bar 4 (h stores + pbuf reuse + hs reuse)

        // H. arrive; prefetch gx[t+1]
        if (tid == 0) red_rel(done_ctr(t + 1, myline));
        if (tid < JPB && t + 1 < SEQ) {
            gxr0 = g_gx[(size_t)(t + 1) * G4 + 0 * H + b * JPB + tid];
            gxr1 = g_gx[(size_t)(t + 1) * G4 + 1 * H + b * JPB + tid];
            gxr2 = g_gx[(size_t)(t + 1) * G4 + 2 * H + b * JPB + tid];
            gxr3 = g_gx[(size_t)(t + 1) * G4 + 3 * H + b * JPB + tid];
        }
    }

    // ---- epilogue: logits[SEQ-1] from h_SEQ ----
    if (tid < NLINES) { while (ld_acq(done_ctr(SEQ, tid)) < PERLINE) {} }
    __syncthreads();
    if (tid < 256)
        ((float4*)hs)[tid] = ((const float4*)(g_h + (size_t)SEQ * H))[tid];
    __syncthreads();
    {
        float s = 0.f;
#pragma unroll
        for (int k = 0; k < 4; k++) {
            float4 hv = hs4[half * 128 + k * 32 + l];
            s += dot4(wout_s[jj * 256 + half * 128 + k * 32 + l], hv);
        }
#pragma unroll
        for (int off = 16; off; off >>= 1) s += __shfl_down_sync(0xffffffffu, s, off);
        if (l == 0) pbuf2[jj * 2 + half] = s;
    }
    __syncthreads();
    if (tid < JPB)
        g_logits[(size_t)(SEQ - 1) * OUTN + b * JPB + tid] =
            pbuf2[tid * 2] + pbuf2[tid * 2 + 1] + boutj;
}

// ---------------- Kernel C: per-row logsumexp ----------------
__global__ void row_lse() {
    const int t = blockIdx.x, tid = threadIdx.x, w = tid >> 5, l = tid & 31;
    __shared__ float red[8];
    float v[4];
#pragma unroll
    for (int k = 0; k < 4; k++) v[k] = g_logits[(size_t)t * OUTN + tid + k * 256];
    float m = fmaxf(fmaxf(v[0], v[1]), fmaxf(v[2], v[3]));
#pragma unroll
    for (int off = 16; off; off >>= 1) m = fmaxf(m, __shfl_xor_sync(0xffffffffu, m, off));
    if (l == 0) red[w] = m;
    __syncthreads();
    float M = red[0];
#pragma unroll
    for (int i = 1; i < 8; i++) M = fmaxf(M, red[i]);
    float s = 0.f;
#pragma unroll
    for (int k = 0; k < 4; k++) s += expf(v[k] - M);
#pragma unroll
    for (int off = 16; off; off >>= 1) s += __shfl_xor_sync(0xffffffffu, s, off);
    __syncthreads();
    if (l == 0) red[w] = s;
    __syncthreads();
    if (tid == 0) {
        float S = 0.f;
#pragma unroll
        for (int i = 0; i < 8; i++) S += red[i];
        g_lse[t] = M + logf(S);
    }
}

// ---------------- Kernel S: bitonic sort each logits row (descending u64 keys) ----------------
__global__ void sort_rows() {
    __shared__ u64 key[OUTN];
    const int t = blockIdx.x, tid = threadIdx.x;

    for (int i = tid; i < OUTN; i += 256) {
        unsigned u = __float_as_uint(g_logits[(size_t)t * OUTN + i]);
        unsigned m = (u & 0x80000000u) ? ~u : (u | 0x80000000u);
        key[i] = ((u64)m << 32) | (u64)(OUTN - 1 - i);
    }
    __syncthreads();

    for (int k = 2; k <= OUTN; k <<= 1) {
        for (int jj = k >> 1; jj > 0; jj >>= 1) {
            for (int i = tid; i < OUTN; i += 256) {
                int ix = i ^ jj;
                if (ix > i) {
                    bool descend = (i & k) == 0;
                    u64 a = key[i], c = key[ix];
                    bool sw = descend ? (a < c) : (a > c);
                    if (sw) { key[i] = c; key[ix] = a; }
                }
            }
            __syncthreads();
        }
    }

    for (int i = tid; i < OUTN; i += 256)
        g_sorted[(size_t)t * OUTN + i] = key[i];
}

// ---------------- Kernel D: ballot-based tour selection over sorted candidates ----------------
__global__ void tour_select(float* __restrict__ out, int out_size) {
    __shared__ unsigned vis[32];
    const int l = threadIdx.x;
    vis[l] = 0;
    __syncwarp();

    u64 cur = g_sorted[l];
    float lse_c = g_lse[0];

    for (int t = 0; t < SEQ; t++) {
        u64 nxt = 0; float lse_n = 0.f;
        if (t + 1 < SEQ) {
            nxt   = g_sorted[(size_t)(t + 1) * OUTN + l];
            lse_n = g_lse[t + 1];
        }

        u64 key = cur;
        int batch = 0;
        unsigned ballot;
        for (;;) {
            unsigned idx = OUTN - 1 - (unsigned)(key & 0xFFFFFFFFu);
            bool unvis = ((vis[idx >> 5] >> (idx & 31)) & 1u) == 0u;
            ballot = __ballot_sync(0xffffffffu, unvis);
            if (ballot) break;
            batch++;
            key = g_sorted[(size_t)t * OUTN + batch * 32 + l];
        }
        int wl = __ffs(ballot) - 1;
        u64 wkey = __shfl_sync(0xffffffffu, key, wl);
        unsigned widx = OUTN - 1 - (unsigned)(wkey & 0xFFFFFFFFu);
        if (l == 0) {
            unsigned m = (unsigned)(wkey >> 32);
            unsigned u = (m & 0x80000000u) ? (m ^ 0x80000000u) : ~m;
            float val = __uint_as_float(u);
            if (t < out_size)       out[t] = (float)widx;
            if (SEQ + t < out_size) out[SEQ + t] = val - lse_c;
            vis[widx >> 5] |= 1u << (widx & 31);
        }
        __syncwarp();

        cur = nxt; lse_c = lse_n;
    }
}

// ---------------- launch ----------------
extern "C" void kernel_launch(void* const* d_in, const int* in_sizes, int n_in,
                              void* d_out, int out_size) {
    const float* X    = (const float*)d_in[0];
    const float* enc  = (const float*)d_in[1];
    const float* Wih  = (const float*)d_in[2];
    const float* Whh  = (const float*)d_in[3];
    const float* bih  = (const float*)d_in[4];
    const float* bhh  = (const float*)d_in[5];
    const float* Wout = (const float*)d_in[6];
    const float* bout = (const float*)d_in[7];
    float* out = (float*)d_out;

    // per-launch counter reset (graph memset node — proven to execute by R14 replays)
    void* doneAddr = nullptr; cudaGetSymbolAddress(&doneAddr, g_done);
    cudaMemsetAsync(doneAddr, 0, (size_t)(SEQ + 1) * NLINES * 32 * sizeof(unsigned));

    precompute_gx<<<dim3(16, 32), 256>>>(X, Wih, bih, bhh);
    lstm_recurrence<<<NB, 512>>>(enc, Whh, Wout, bout);
    row_lse<<<SEQ, 256>>>();
    sort_rows<<<SEQ, 256>>>();
    tour_select<<<1, 32>>>(out, out_size);
}